// round 1
// baseline (speedup 1.0000x reference)
#include <cuda_runtime.h>
#include <cstdint>

// ---------------- problem constants ----------------
#define BATCH      4096
#define NDIMS      19
#define D          256
#define NROWS      8192           // 2*BATCH
#define JSPLIT     4
#define JCHUNK     (NROWS / JSPLIT)   // 2048
#define IBLK       128
#define WROWS      16             // rows per warp (8 warps * 16 = 128)
#define INV_T      14.285714285714286f   // 1/0.07
#define NEG_INIT   (-1.0e30f)
#define MASK_VAL   (-3.0e38f)

// ---------------- device scratch (no allocs allowed) ----------------
__device__ float  g_Z [NROWS * D];    // normalized embeddings, row-major
__device__ float  g_Zt[D * NROWS];    // normalized embeddings, transposed [k][row]
__device__ int    g_pieces[NROWS];
__device__ float2 g_part[JSPLIT * NROWS];   // per-(jsplit,row) partial (m, s)
__device__ float  g_rowSum[NROWS];
__device__ int    g_rowCnt[NROWS];
__device__ float  g_rankSum;
__device__ int    g_rankCnt;

// ---------------- packed fp32x2 helpers (sm_100+) ----------------
__device__ __forceinline__ unsigned long long fma2(unsigned long long a,
                                                   unsigned long long b,
                                                   unsigned long long c) {
    unsigned long long d;
    asm("fma.rn.f32x2 %0, %1, %2, %3;" : "=l"(d) : "l"(a), "l"(b), "l"(c));
    return d;
}
__device__ __forceinline__ unsigned long long dup2(float x) {
    unsigned long long d;
    asm("mov.b64 %0, {%1, %1};" : "=l"(d) : "f"(x));
    return d;
}
__device__ __forceinline__ void lds2(uint32_t addr, unsigned long long& x,
                                     unsigned long long& y) {
    asm("ld.shared.v2.u64 {%0, %1}, [%2];" : "=l"(x), "=l"(y) : "r"(addr));
}
__device__ __forceinline__ void unpack2(unsigned long long p, float& lo, float& hi) {
    asm("mov.b64 {%0, %1}, %2;" : "=f"(lo), "=f"(hi) : "l"(p));
}

__device__ __forceinline__ void lse_upd(float dot, bool isneg, float& m, float& s) {
    float x  = isneg ? dot * INV_T : MASK_VAL;
    float mn = fmaxf(m, x);
    s = s * __expf(m - mn) + __expf(x - mn);
    m = mn;
}

// ---------------- kernel 1: normalize + concat + transpose ----------------
__global__ void normalize_kernel(const float* __restrict__ za,
                                 const float* __restrict__ zb,
                                 const int*   __restrict__ pa,
                                 const int*   __restrict__ pb) {
    int warp = threadIdx.x >> 5;
    int lane = threadIdx.x & 31;
    int row  = blockIdx.x * 8 + warp;
    const float* src = (row < BATCH) ? (za + (size_t)row * D)
                                     : (zb + (size_t)(row - BATCH) * D);
    int k0 = lane * 4;
    float4 v0 = *(const float4*)(src + k0);
    float4 v1 = *(const float4*)(src + k0 + 128);
    float ss = v0.x*v0.x + v0.y*v0.y + v0.z*v0.z + v0.w*v0.w
             + v1.x*v1.x + v1.y*v1.y + v1.z*v1.z + v1.w*v1.w;
    #pragma unroll
    for (int off = 16; off; off >>= 1) ss += __shfl_xor_sync(0xffffffffu, ss, off);
    float inv = 1.0f / fmaxf(sqrtf(ss), 1e-8f);
    v0.x *= inv; v0.y *= inv; v0.z *= inv; v0.w *= inv;
    v1.x *= inv; v1.y *= inv; v1.z *= inv; v1.w *= inv;
    *(float4*)(g_Z + (size_t)row * D + k0)       = v0;
    *(float4*)(g_Z + (size_t)row * D + k0 + 128) = v1;
    g_Zt[(size_t)(k0 + 0)   * NROWS + row] = v0.x;
    g_Zt[(size_t)(k0 + 1)   * NROWS + row] = v0.y;
    g_Zt[(size_t)(k0 + 2)   * NROWS + row] = v0.z;
    g_Zt[(size_t)(k0 + 3)   * NROWS + row] = v0.w;
    g_Zt[(size_t)(k0 + 128) * NROWS + row] = v1.x;
    g_Zt[(size_t)(k0 + 129) * NROWS + row] = v1.y;
    g_Zt[(size_t)(k0 + 130) * NROWS + row] = v1.z;
    g_Zt[(size_t)(k0 + 131) * NROWS + row] = v1.w;
    if (lane == 0)
        g_pieces[row] = (row < BATCH) ? pa[row] : pb[row - BATCH];
}

// ---------------- kernel 2: fused sim GEMM + online masked logsumexp ----------------
__global__ void __launch_bounds__(256, 1) phaseA_kernel() {
    extern __shared__ float ziT[];            // [D][IBLK], k-major, row pairs contiguous
    const int tid   = threadIdx.x;
    const int i0    = blockIdx.x * IBLK;
    const int jbase = blockIdx.y * JCHUNK;

    // cooperative tile load (transposed into smem)
    for (int t = tid; t < IBLK * D; t += 256) {
        int row = t >> 8;          // t / D
        int k   = t & 255;         // t % D
        ziT[k * IBLK + row] = g_Z[(size_t)(i0 + row) * D + k];
    }
    __syncthreads();

    const int warp = tid >> 5;
    const int lane = tid & 31;
    const int wr0  = warp * WROWS;

    int pi_[WROWS];
    #pragma unroll
    for (int r = 0; r < WROWS; r++) pi_[r] = g_pieces[i0 + wr0 + r];

    float m[WROWS], s[WROWS];
    #pragma unroll
    for (int r = 0; r < WROWS; r++) { m[r] = NEG_INIT; s[r] = 0.f; }

    const uint32_t sbase = (uint32_t)__cvta_generic_to_shared(ziT) + wr0 * 4;

    for (int jj = lane; jj < JCHUNK; jj += 32) {
        const int j  = jbase + jj;
        const int pj = g_pieces[j];
        const float* p = g_Zt + j;

        unsigned long long acc[8];
        #pragma unroll
        for (int r = 0; r < 8; r++) acc[r] = 0ull;

        #pragma unroll 2
        for (int kc = 0; kc < D; kc += 8) {
            float zj[8];
            #pragma unroll
            for (int u = 0; u < 8; u++) zj[u] = p[(size_t)u * NROWS];
            p += (size_t)8 * NROWS;
            #pragma unroll
            for (int u = 0; u < 8; u++) {
                unsigned long long b = dup2(zj[u]);
                uint32_t a = sbase + (uint32_t)(kc + u) * (IBLK * 4);
                unsigned long long p0, p1, p2, p3, p4, p5, p6, p7;
                lds2(a,      p0, p1);
                lds2(a + 16, p2, p3);
                lds2(a + 32, p4, p5);
                lds2(a + 48, p6, p7);
                acc[0] = fma2(b, p0, acc[0]);
                acc[1] = fma2(b, p1, acc[1]);
                acc[2] = fma2(b, p2, acc[2]);
                acc[3] = fma2(b, p3, acc[3]);
                acc[4] = fma2(b, p4, acc[4]);
                acc[5] = fma2(b, p5, acc[5]);
                acc[6] = fma2(b, p6, acc[6]);
                acc[7] = fma2(b, p7, acc[7]);
            }
        }
        #pragma unroll
        for (int r = 0; r < 8; r++) {
            float d0, d1;
            unpack2(acc[r], d0, d1);
            lse_upd(d0, pj != pi_[2 * r],     m[2 * r],     s[2 * r]);
            lse_upd(d1, pj != pi_[2 * r + 1], m[2 * r + 1], s[2 * r + 1]);
        }
    }

    // warp-level (m, s) merge per row, deterministic
    #pragma unroll
    for (int r = 0; r < WROWS; r++) {
        #pragma unroll
        for (int off = 16; off; off >>= 1) {
            float mo = __shfl_down_sync(0xffffffffu, m[r], off);
            float so = __shfl_down_sync(0xffffffffu, s[r], off);
            float mn = fmaxf(m[r], mo);
            s[r] = s[r] * __expf(m[r] - mn) + so * __expf(mo - mn);
            m[r] = mn;
        }
        if (lane == 0)
            g_part[blockIdx.y * NROWS + (i0 + wr0 + r)] = make_float2(m[r], s[r]);
    }
}

// ---------------- kernel 3: ranking loss (single CTA, deterministic) ----------------
__global__ void ranking_kernel(const float* __restrict__ logits,
                               const float* __restrict__ la,
                               const float* __restrict__ lb) {
    __shared__ float ssum[1024];
    __shared__ int   scnt[1024];
    int tid = threadIdx.x;
    float sum = 0.f; int cnt = 0;
    for (int i = tid; i < BATCH * NDIMS; i += 1024) {
        float diff = la[i] - lb[i];
        if (fabsf(diff) >= 0.05f) {
            float t = (diff > 0.f ? 0.9f : 0.f) + 0.05f;
            float l = logits[i];
            sum += fmaxf(l, 0.f) - l * t + log1pf(__expf(-fabsf(l)));
            cnt++;
        }
    }
    ssum[tid] = sum; scnt[tid] = cnt;
    __syncthreads();
    for (int o = 512; o; o >>= 1) {
        if (tid < o) { ssum[tid] += ssum[tid + o]; scnt[tid] += scnt[tid + o]; }
        __syncthreads();
    }
    if (tid == 0) { g_rankSum = ssum[0]; g_rankCnt = scnt[0]; }
}

// ---------------- kernel 4: positives pass (per-row) ----------------
__global__ void phaseB_kernel() {
    __shared__ float zi[D];
    __shared__ float snl;
    __shared__ int   shn;
    __shared__ float ssum[256];
    __shared__ int   scnt[256];
    const int i   = blockIdx.x;
    const int tid = threadIdx.x;
    zi[tid] = g_Z[(size_t)i * D + tid];
    if (tid == 0) {
        float m = NEG_INIT, s = 0.f;
        #pragma unroll
        for (int p = 0; p < JSPLIT; p++) {
            float2 ms = g_part[p * NROWS + i];
            float mn = fmaxf(m, ms.x);
            s = s * __expf(m - mn) + ms.y * __expf(ms.x - mn);
            m = mn;
        }
        shn = (s > 0.f);
        snl = m + logf(s);
    }
    __syncthreads();
    const float nl = snl;
    const int   hn = shn;
    const int   pi = g_pieces[i];
    float sum = 0.f; int cnt = 0;
    if (hn) {
        for (int j = tid; j < NROWS; j += 256) {
            if (j != i && g_pieces[j] == pi) {
                const float4* zj4 = (const float4*)(g_Z + (size_t)j * D);
                const float4* zi4 = (const float4*)zi;
                float d = 0.f;
                #pragma unroll 8
                for (int k = 0; k < D / 4; k++) {
                    float4 a = zi4[k], b = zj4[k];
                    d += a.x * b.x + a.y * b.y + a.z * b.z + a.w * b.w;
                }
                float sim = d * INV_T;
                sum += log1pf(__expf(nl - sim));
                cnt++;
            }
        }
    }
    ssum[tid] = sum; scnt[tid] = cnt;
    __syncthreads();
    for (int o = 128; o; o >>= 1) {
        if (tid < o) { ssum[tid] += ssum[tid + o]; scnt[tid] += scnt[tid + o]; }
        __syncthreads();
    }
    if (tid == 0) { g_rowSum[i] = ssum[0]; g_rowCnt[i] = scnt[0]; }
}

// ---------------- kernel 5: final deterministic reduce + output ----------------
__global__ void final_kernel(float* __restrict__ out, int out_size) {
    __shared__ float ssum[256];
    __shared__ int   scnt[256];
    int tid = threadIdx.x;
    float sum = 0.f; int cnt = 0;
    for (int i = tid; i < NROWS; i += 256) { sum += g_rowSum[i]; cnt += g_rowCnt[i]; }
    ssum[tid] = sum; scnt[tid] = cnt;
    __syncthreads();
    for (int o = 128; o; o >>= 1) {
        if (tid < o) { ssum[tid] += ssum[tid + o]; scnt[tid] += scnt[tid + o]; }
        __syncthreads();
    }
    if (tid == 0) {
        float lcon  = (scnt[0] > 0) ? (ssum[0] / (float)scnt[0]) : 0.f;
        float lrank = (g_rankCnt > 0) ? (g_rankSum / (float)g_rankCnt) : 0.f;
        out[0] = lrank + 0.3f * lcon;
        if (out_size > 1) out[1] = lrank;
        if (out_size > 2) out[2] = lcon;
    }
}

// ---------------- launch ----------------
extern "C" void kernel_launch(void* const* d_in, const int* in_sizes, int n_in,
                              void* d_out, int out_size) {
    const float* za     = (const float*)d_in[0];
    const float* zb     = (const float*)d_in[1];
    const float* logits = (const float*)d_in[2];
    const float* la     = (const float*)d_in[3];
    const float* lb     = (const float*)d_in[4];
    const int*   pa     = (const int*)d_in[5];
    const int*   pb     = (const int*)d_in[6];
    float* out = (float*)d_out;

    cudaFuncSetAttribute(phaseA_kernel,
                         cudaFuncAttributeMaxDynamicSharedMemorySize,
                         IBLK * D * (int)sizeof(float));

    normalize_kernel<<<NROWS / 8, 256>>>(za, zb, pa, pb);
    ranking_kernel<<<1, 1024>>>(logits, la, lb);
    phaseA_kernel<<<dim3(NROWS / IBLK, JSPLIT), 256, IBLK * D * sizeof(float)>>>();
    phaseB_kernel<<<NROWS, 256>>>();
    final_kernel<<<1, 256>>>(out, out_size);
}

// round 3
// speedup vs baseline: 8.7909x; 8.7909x over previous
#include <cuda_runtime.h>
#include <cuda_bf16.h>
#include <cstdint>

// ---------------- problem constants ----------------
#define BATCH    4096
#define NDIMS    19
#define D        256
#define NROWS    8192
#define JSPLIT   2
#define JCHUNK   (NROWS / JSPLIT)      // 4096
#define NT       (JCHUNK / 128)        // 32 j-tiles per CTA
#define IBLK     128
#define INV_T    14.285714285714286f
#define C2EXP    (14.285714285714286f * 1.4426950408889634f)   // INV_T * log2(e)
#define REGIONS  8                     // JSPLIT * 4 n-warps
#define CAP      16                    // positive slots per (row, region, quad)
#define TSTRIDE  528                   // padded row stride (bytes) -> conflict-free
#define TILEB    (128 * TSTRIDE)       // 67584 bytes per tile

// ---------------- device scratch ----------------
__device__ uint32_t g_Zbf[NROWS * D / 2];       // normalized bf16 rows (2 per u32)
__device__ int      g_pieces[NROWS];
__device__ float    g_negS[REGIONS * NROWS];
__device__ int      g_posCnt[NROWS * REGIONS * 4];
__device__ float    g_posSim[(size_t)NROWS * REGIONS * 4 * CAP];   // 16 MB
__device__ float    g_rowSum[NROWS];
__device__ int      g_rowCnt[NROWS];
__device__ float    g_rankS[64];
__device__ int      g_rankC[64];

// ---------------- helpers ----------------
__device__ __forceinline__ uint32_t smem_u32(const void* p) {
    return (uint32_t)__cvta_generic_to_shared(p);
}
__device__ __forceinline__ float ex2(float x) {
    float r;
    asm("ex2.approx.f32 %0, %1;" : "=f"(r) : "f"(x));
    return r;
}
__device__ __forceinline__ void mma16816(float d[4], const uint32_t a[4],
                                         const uint32_t b[2]) {
    asm volatile(
        "mma.sync.aligned.m16n8k16.row.col.f32.bf16.bf16.f32 "
        "{%0,%1,%2,%3}, {%4,%5,%6,%7}, {%8,%9}, {%0,%1,%2,%3};\n"
        : "+f"(d[0]), "+f"(d[1]), "+f"(d[2]), "+f"(d[3])
        : "r"(a[0]), "r"(a[1]), "r"(a[2]), "r"(a[3]), "r"(b[0]), "r"(b[1]));
}
__device__ __forceinline__ void cp16(uint32_t dst, const void* src) {
    uint64_t gs;
    asm("cvta.to.global.u64 %0, %1;" : "=l"(gs) : "l"(src));
    asm volatile("cp.async.cg.shared.global [%0], [%1], 16;" :: "r"(dst), "l"(gs));
}
#define CP_COMMIT() asm volatile("cp.async.commit_group;" ::: "memory")
#define CP_WAIT0()  asm volatile("cp.async.wait_group 0;" ::: "memory")

// load 128x256 bf16 tile (rows row0..row0+127 of g_Zbf) into padded smem layout
__device__ __forceinline__ void cp_tile(uint32_t dstBase, int row0) {
    const char* src = (const char*)g_Zbf + (size_t)row0 * 512;
    #pragma unroll
    for (int it = 0; it < 16; it++) {
        int idx = it * 256 + threadIdx.x;
        int r = idx >> 5, c = idx & 31;
        cp16(dstBase + r * TSTRIDE + c * 16, src + r * 512 + c * 16);
    }
}

// ---------------- kernel 1: normalize -> bf16 ----------------
__global__ void normalize_kernel(const float* __restrict__ za,
                                 const float* __restrict__ zb,
                                 const int*   __restrict__ pa,
                                 const int*   __restrict__ pb) {
    int warp = threadIdx.x >> 5;
    int lane = threadIdx.x & 31;
    int row  = blockIdx.x * 8 + warp;
    const float* src = (row < BATCH) ? (za + (size_t)row * D)
                                     : (zb + (size_t)(row - BATCH) * D);
    int k0 = lane * 4;
    float4 v0 = *(const float4*)(src + k0);
    float4 v1 = *(const float4*)(src + k0 + 128);
    float ss = v0.x*v0.x + v0.y*v0.y + v0.z*v0.z + v0.w*v0.w
             + v1.x*v1.x + v1.y*v1.y + v1.z*v1.z + v1.w*v1.w;
    #pragma unroll
    for (int off = 16; off; off >>= 1) ss += __shfl_xor_sync(0xffffffffu, ss, off);
    float inv = 1.0f / fmaxf(sqrtf(ss), 1e-8f);

    __nv_bfloat162 b0 = __floats2bfloat162_rn(v0.x * inv, v0.y * inv);
    __nv_bfloat162 b1 = __floats2bfloat162_rn(v0.z * inv, v0.w * inv);
    __nv_bfloat162 b2 = __floats2bfloat162_rn(v1.x * inv, v1.y * inv);
    __nv_bfloat162 b3 = __floats2bfloat162_rn(v1.z * inv, v1.w * inv);
    uint32_t* dst = g_Zbf + (size_t)row * 128;
    dst[lane * 2]          = *reinterpret_cast<uint32_t*>(&b0);
    dst[lane * 2 + 1]      = *reinterpret_cast<uint32_t*>(&b1);
    dst[64 + lane * 2]     = *reinterpret_cast<uint32_t*>(&b2);
    dst[64 + lane * 2 + 1] = *reinterpret_cast<uint32_t*>(&b3);
    if (lane == 0)
        g_pieces[row] = (row < BATCH) ? pa[row] : pb[row - BATCH];
}

// ---------------- kernel 2: HMMA GEMM + fused masked LSE ----------------
__global__ void __launch_bounds__(256, 1) simlse_kernel() {
    extern __shared__ uint8_t dsm[];
    __shared__ int s_pi[128];
    __shared__ int s_pj[2][128];

    const int tid  = threadIdx.x;
    const int warp = tid >> 5;
    const int lane = tid & 31;
    const int wm = warp >> 2;         // 0..1 (m)
    const int wn = warp & 3;          // 0..3 (n)
    const int q  = lane >> 2;         // 0..7
    const int a4 = (lane & 3) * 4;    // byte offset within 16B chunk

    const int ib = blockIdx.x, js = blockIdx.y;
    const int i0 = ib * IBLK;
    const int jbase = js * JCHUNK;
    const int region = js * 4 + wn;

    const uint32_t sbase = smem_u32(dsm);

    if (tid < 128) {
        s_pi[tid]    = g_pieces[i0 + tid];
        s_pj[0][tid] = g_pieces[jbase + tid];
    }

    cp_tile(sbase, i0);               // A tile at offset 0
    cp_tile(sbase + TILEB, jbase);    // B0
    CP_COMMIT();
    CP_WAIT0();
    __syncthreads();

    // per-lane constants
    int   mypc[8], igr[8];
    float* pptr[8];
    #pragma unroll
    for (int mt = 0; mt < 4; mt++)
        #pragma unroll
        for (int h = 0; h < 2; h++) {
            int ridx = mt * 2 + h;
            int rloc = wm * 64 + mt * 16 + q + 8 * h;
            mypc[ridx] = s_pi[rloc];
            igr[ridx]  = i0 + rloc;
            pptr[ridx] = g_posSim + ((size_t)igr[ridx] * REGIONS + region) * (4 * CAP)
                       + (lane & 3) * CAP;
        }

    float negacc[8];
    int   pcnt[8];
    #pragma unroll
    for (int r = 0; r < 8; r++) { negacc[r] = 0.f; pcnt[r] = 0; }

    const uint32_t offA = (uint32_t)(wm * 64 + q) * TSTRIDE + a4;
    const uint32_t offBl = (uint32_t)(wn * 32 + q) * TSTRIDE + a4;

    for (int t = 0; t < NT; ++t) {
        if (t + 1 < NT) {
            cp_tile(sbase + TILEB + ((t + 1) & 1) * TILEB, jbase + (t + 1) * 128);
            CP_COMMIT();
            if (tid < 128)
                s_pj[(t + 1) & 1][tid] = g_pieces[jbase + (t + 1) * 128 + tid];
        }

        // ---- MMA: 128x128 <- A(128x256) * B(128x256)^T ----
        float acc[4][4][4];
        #pragma unroll
        for (int mt = 0; mt < 4; mt++)
            #pragma unroll
            for (int nt = 0; nt < 4; nt++)
                #pragma unroll
                for (int e = 0; e < 4; e++) acc[mt][nt][e] = 0.f;

        const uint32_t offB = TILEB + (uint32_t)(t & 1) * TILEB + offBl;

        #pragma unroll
        for (int ks = 0; ks < 16; ks++) {
            uint32_t a[4][4], b[4][2];
            #pragma unroll
            for (int mt = 0; mt < 4; mt++) {
                uint32_t base = offA + (uint32_t)mt * (16 * TSTRIDE) + ks * 32;
                a[mt][0] = *(const uint32_t*)(dsm + base);
                a[mt][1] = *(const uint32_t*)(dsm + base + 8 * TSTRIDE);
                a[mt][2] = *(const uint32_t*)(dsm + base + 16);
                a[mt][3] = *(const uint32_t*)(dsm + base + 8 * TSTRIDE + 16);
            }
            #pragma unroll
            for (int nt = 0; nt < 4; nt++) {
                uint32_t base = offB + (uint32_t)nt * (8 * TSTRIDE) + ks * 32;
                b[nt][0] = *(const uint32_t*)(dsm + base);
                b[nt][1] = *(const uint32_t*)(dsm + base + 16);
            }
            #pragma unroll
            for (int mt = 0; mt < 4; mt++)
                #pragma unroll
                for (int nt = 0; nt < 4; nt++)
                    mma16816(acc[mt][nt], a[mt], b[nt]);
        }

        // ---- fused epilogue ----
        const int* pjrow = s_pj[t & 1];
        const int j0 = jbase + t * 128 + wn * 32 + (lane & 3) * 2;
        int pjc[8];
        #pragma unroll
        for (int nt = 0; nt < 4; nt++) {
            pjc[nt * 2]     = pjrow[wn * 32 + nt * 8 + (lane & 3) * 2];
            pjc[nt * 2 + 1] = pjrow[wn * 32 + nt * 8 + (lane & 3) * 2 + 1];
        }
        #pragma unroll
        for (int mt = 0; mt < 4; mt++)
            #pragma unroll
            for (int h = 0; h < 2; h++) {
                const int ridx = mt * 2 + h;
                const int myp = mypc[ridx];
                float na = 0.f;
                #pragma unroll
                for (int nt = 0; nt < 4; nt++)
                    #pragma unroll
                    for (int cc = 0; cc < 2; cc++) {
                        float dot = acc[mt][nt][h * 2 + cc];
                        float e = ex2(fmaf(dot, C2EXP, -C2EXP));
                        bool same = (pjc[nt * 2 + cc] == myp);
                        na += same ? 0.f : e;
                        if (same) {
                            int jg = j0 + nt * 8 + cc;
                            if (jg != igr[ridx]) {
                                if (pcnt[ridx] < CAP)
                                    pptr[ridx][pcnt[ridx]] = dot * INV_T;
                                pcnt[ridx]++;
                            }
                        }
                    }
                negacc[ridx] += na;
            }

        CP_WAIT0();
        __syncthreads();
    }

    // ---- write per-(row, region) results ----
    #pragma unroll
    for (int ridx = 0; ridx < 8; ridx++) {
        float v = negacc[ridx];
        v += __shfl_xor_sync(0xffffffffu, v, 1);
        v += __shfl_xor_sync(0xffffffffu, v, 2);
        if ((lane & 3) == 0)
            g_negS[region * NROWS + igr[ridx]] = v;
        g_posCnt[(igr[ridx] * REGIONS + region) * 4 + (lane & 3)] =
            (pcnt[ridx] > CAP) ? CAP : pcnt[ridx];
    }
}

// ---------------- kernel 3: ranking loss partials ----------------
__global__ void ranking_kernel(const float* __restrict__ logits,
                               const float* __restrict__ la,
                               const float* __restrict__ lb) {
    __shared__ float ssum[256];
    __shared__ int   scnt[256];
    int tid = threadIdx.x;
    float sum = 0.f; int cnt = 0;
    for (int i = blockIdx.x * 256 + tid; i < BATCH * NDIMS; i += 64 * 256) {
        float diff = la[i] - lb[i];
        if (fabsf(diff) >= 0.05f) {
            float t = (diff > 0.f ? 0.9f : 0.f) + 0.05f;
            float l = logits[i];
            sum += fmaxf(l, 0.f) - l * t + log1pf(__expf(-fabsf(l)));
            cnt++;
        }
    }
    ssum[tid] = sum; scnt[tid] = cnt;
    __syncthreads();
    for (int o = 128; o; o >>= 1) {
        if (tid < o) { ssum[tid] += ssum[tid + o]; scnt[tid] += scnt[tid + o]; }
        __syncthreads();
    }
    if (tid == 0) { g_rankS[blockIdx.x] = ssum[0]; g_rankC[blockIdx.x] = scnt[0]; }
}

// ---------------- kernel 4: per-row merge ----------------
__global__ void final_row_kernel() {
    int i = blockIdx.x * 256 + threadIdx.x;
    float S = 0.f;
    #pragma unroll
    for (int r = 0; r < REGIONS; r++) S += g_negS[r * NROWS + i];
    float sum = 0.f; int cnt = 0;
    if (S > 0.f) {
        float nl = INV_T + logf(S);
        const float* pb = g_posSim + (size_t)i * (REGIONS * 4 * CAP);
        const int*   pc = g_posCnt + i * (REGIONS * 4);
        #pragma unroll
        for (int r = 0; r < REGIONS; r++)
            #pragma unroll
            for (int qd = 0; qd < 4; qd++) {
                int n = pc[r * 4 + qd];
                cnt += n;
                for (int s = 0; s < n; s++) {
                    float sim = pb[(r * 4 + qd) * CAP + s];
                    float d = nl - sim;
                    sum += (d > 0.f) ? (d + log1pf(__expf(-d))) : log1pf(__expf(d));
                }
            }
    }
    g_rowSum[i] = sum;
    g_rowCnt[i] = cnt;
}

// ---------------- kernel 5: final deterministic reduce ----------------
__global__ void final_kernel(float* __restrict__ out, int out_size) {
    __shared__ float ssum[256];
    __shared__ int   scnt[256];
    int tid = threadIdx.x;
    float sum = 0.f; int cnt = 0;
    for (int i = tid; i < NROWS; i += 256) { sum += g_rowSum[i]; cnt += g_rowCnt[i]; }
    ssum[tid] = sum; scnt[tid] = cnt;
    __syncthreads();
    for (int o = 128; o; o >>= 1) {
        if (tid < o) { ssum[tid] += ssum[tid + o]; scnt[tid] += scnt[tid + o]; }
        __syncthreads();
    }
    if (tid == 0) {
        float rs = 0.f; int rc = 0;
        for (int b = 0; b < 64; b++) { rs += g_rankS[b]; rc += g_rankC[b]; }
        float lcon  = (scnt[0] > 0) ? (ssum[0] / (float)scnt[0]) : 0.f;
        float lrank = (rc > 0) ? (rs / (float)rc) : 0.f;
        out[0] = lrank + 0.3f * lcon;
        if (out_size > 1) out[1] = lrank;
        if (out_size > 2) out[2] = lcon;
    }
}

// ---------------- launch ----------------
extern "C" void kernel_launch(void* const* d_in, const int* in_sizes, int n_in,
                              void* d_out, int out_size) {
    const float* za     = (const float*)d_in[0];
    const float* zb     = (const float*)d_in[1];
    const float* logits = (const float*)d_in[2];
    const float* la     = (const float*)d_in[3];
    const float* lb     = (const float*)d_in[4];
    const int*   pa     = (const int*)d_in[5];
    const int*   pb     = (const int*)d_in[6];
    float* out = (float*)d_out;

    const int dynSmem = 3 * TILEB;   // A + B0 + B1 = 202752 bytes
    cudaFuncSetAttribute(simlse_kernel,
                         cudaFuncAttributeMaxDynamicSharedMemorySize, dynSmem);

    normalize_kernel<<<NROWS / 8, 256>>>(za, zb, pa, pb);
    ranking_kernel<<<64, 256>>>(logits, la, lb);
    simlse_kernel<<<dim3(NROWS / IBLK, JSPLIT), 256, dynSmem>>>();
    final_row_kernel<<<NROWS / 256, 256>>>();
    final_kernel<<<1, 256>>>(out, out_size);
}

// round 4
// speedup vs baseline: 10.1857x; 1.1587x over previous
#include <cuda_runtime.h>
#include <cuda_bf16.h>
#include <cstdint>

// ---------------- problem constants ----------------
#define BATCH    4096
#define NDIMS    19
#define D        256
#define NROWS    8192
#define JSPLIT   2
#define JCHUNK   (NROWS / JSPLIT)      // 4096
#define NT       (JCHUNK / 128)        // 32 j-tiles per CTA
#define IBLK     128
#define INV_T    14.285714285714286f
#define C2EXP    (14.285714285714286f * 1.4426950408889634f)   // INV_T * log2(e)
#define REGIONS  8                     // JSPLIT * 4 n-warps
#define CAP      16                    // positive slots per (row, region, quad)
#define TSTRIDE  528                   // padded row stride (bytes) -> conflict-free
#define TILEB    (128 * TSTRIDE)       // 67584 bytes per tile

// ---------------- device scratch ----------------
__device__ uint32_t g_Zbf[NROWS * D / 2];       // normalized bf16 rows (2 per u32)
__device__ int      g_pieces[NROWS];
__device__ float    g_negS[REGIONS * NROWS];
__device__ int      g_posCnt[NROWS * REGIONS * 4];
__device__ float    g_posSim[(size_t)NROWS * REGIONS * 4 * CAP];   // 16 MB
__device__ float    g_rowSum[NROWS];
__device__ int      g_rowCnt[NROWS];
__device__ float    g_rankS[64];
__device__ int      g_rankC[64];

// ---------------- helpers ----------------
__device__ __forceinline__ uint32_t smem_u32(const void* p) {
    return (uint32_t)__cvta_generic_to_shared(p);
}
__device__ __forceinline__ float ex2(float x) {
    float r;
    asm("ex2.approx.f32 %0, %1;" : "=f"(r) : "f"(x));
    return r;
}
__device__ __forceinline__ void mma16816(float d[4], const uint32_t a[4],
                                         const uint32_t b[2]) {
    asm volatile(
        "mma.sync.aligned.m16n8k16.row.col.f32.bf16.bf16.f32 "
        "{%0,%1,%2,%3}, {%4,%5,%6,%7}, {%8,%9}, {%0,%1,%2,%3};\n"
        : "+f"(d[0]), "+f"(d[1]), "+f"(d[2]), "+f"(d[3])
        : "r"(a[0]), "r"(a[1]), "r"(a[2]), "r"(a[3]), "r"(b[0]), "r"(b[1]));
}
__device__ __forceinline__ void ldsm4(uint32_t addr, uint32_t r[4]) {
    asm volatile("ldmatrix.sync.aligned.m8n8.x4.shared.b16 {%0,%1,%2,%3}, [%4];"
                 : "=r"(r[0]), "=r"(r[1]), "=r"(r[2]), "=r"(r[3]) : "r"(addr));
}
__device__ __forceinline__ void cp16(uint32_t dst, const void* src) {
    uint64_t gs;
    asm("cvta.to.global.u64 %0, %1;" : "=l"(gs) : "l"(src));
    asm volatile("cp.async.cg.shared.global [%0], [%1], 16;" :: "r"(dst), "l"(gs));
}
#define CP_COMMIT() asm volatile("cp.async.commit_group;" ::: "memory")
#define CP_WAIT0()  asm volatile("cp.async.wait_group 0;" ::: "memory")

// load 128x256 bf16 tile (rows row0..row0+127 of g_Zbf) into padded smem layout
__device__ __forceinline__ void cp_tile(uint32_t dstBase, int row0) {
    const char* src = (const char*)g_Zbf + (size_t)row0 * 512;
    #pragma unroll
    for (int it = 0; it < 16; it++) {
        int idx = it * 256 + threadIdx.x;
        int r = idx >> 5, c = idx & 31;
        cp16(dstBase + r * TSTRIDE + c * 16, src + r * 512 + c * 16);
    }
}

// ---------------- kernel 1: normalize -> bf16 ----------------
__global__ void normalize_kernel(const float* __restrict__ za,
                                 const float* __restrict__ zb,
                                 const int*   __restrict__ pa,
                                 const int*   __restrict__ pb) {
    int warp = threadIdx.x >> 5;
    int lane = threadIdx.x & 31;
    int row  = blockIdx.x * 8 + warp;
    const float* src = (row < BATCH) ? (za + (size_t)row * D)
                                     : (zb + (size_t)(row - BATCH) * D);
    int k0 = lane * 4;
    float4 v0 = *(const float4*)(src + k0);
    float4 v1 = *(const float4*)(src + k0 + 128);
    float ss = v0.x*v0.x + v0.y*v0.y + v0.z*v0.z + v0.w*v0.w
             + v1.x*v1.x + v1.y*v1.y + v1.z*v1.z + v1.w*v1.w;
    #pragma unroll
    for (int off = 16; off; off >>= 1) ss += __shfl_xor_sync(0xffffffffu, ss, off);
    float inv = 1.0f / fmaxf(sqrtf(ss), 1e-8f);

    __nv_bfloat162 b0 = __floats2bfloat162_rn(v0.x * inv, v0.y * inv);
    __nv_bfloat162 b1 = __floats2bfloat162_rn(v0.z * inv, v0.w * inv);
    __nv_bfloat162 b2 = __floats2bfloat162_rn(v1.x * inv, v1.y * inv);
    __nv_bfloat162 b3 = __floats2bfloat162_rn(v1.z * inv, v1.w * inv);
    uint32_t* dst = g_Zbf + (size_t)row * 128;
    dst[lane * 2]          = *reinterpret_cast<uint32_t*>(&b0);
    dst[lane * 2 + 1]      = *reinterpret_cast<uint32_t*>(&b1);
    dst[64 + lane * 2]     = *reinterpret_cast<uint32_t*>(&b2);
    dst[64 + lane * 2 + 1] = *reinterpret_cast<uint32_t*>(&b3);
    if (lane == 0)
        g_pieces[row] = (row < BATCH) ? pa[row] : pb[row - BATCH];
}

// ---------------- kernel 2: HMMA GEMM + fused masked LSE ----------------
__global__ void __launch_bounds__(256, 1) simlse_kernel() {
    extern __shared__ uint8_t dsm[];
    __shared__ int s_pi[128];
    __shared__ int s_pj[2][128];

    const int tid  = threadIdx.x;
    const int warp = tid >> 5;
    const int lane = tid & 31;
    const int wm = warp >> 2;         // 0..1 (m)
    const int wn = warp & 3;          // 0..3 (n)
    const int q  = lane >> 2;         // 0..7

    const int ib = blockIdx.x, js = blockIdx.y;
    const int i0 = ib * IBLK;
    const int jbase = js * JCHUNK;
    const int region = js * 4 + wn;

    const uint32_t sbase = smem_u32(dsm);

    if (tid < 128) {
        s_pi[tid]    = g_pieces[i0 + tid];
        s_pj[0][tid] = g_pieces[jbase + tid];
    }

    cp_tile(sbase, i0);               // A tile at offset 0
    cp_tile(sbase + TILEB, jbase);    // B0
    CP_COMMIT();
    CP_WAIT0();
    __syncthreads();

    // per-lane constants
    int   mypc[8], igr[8];
    float* pptr[8];
    #pragma unroll
    for (int mt = 0; mt < 4; mt++)
        #pragma unroll
        for (int h = 0; h < 2; h++) {
            int ridx = mt * 2 + h;
            int rloc = wm * 64 + mt * 16 + q + 8 * h;
            mypc[ridx] = s_pi[rloc];
            igr[ridx]  = i0 + rloc;
            pptr[ridx] = g_posSim + ((size_t)igr[ridx] * REGIONS + region) * (4 * CAP)
                       + (lane & 3) * CAP;
        }

    float negacc[8];
    int   pcnt[8];
    #pragma unroll
    for (int r = 0; r < 8; r++) { negacc[r] = 0.f; pcnt[r] = 0; }

    // ldmatrix lane addresses
    // A (.x4): groups [m0-7 k0 | m8-15 k0 | m0-7 k+16B | m8-15 k+16B]
    const uint32_t aLane = sbase
        + (uint32_t)(wm * 64 + (lane & 15)) * TSTRIDE + (uint32_t)(lane >> 4) * 16;
    // B (.x4): groups [n0-7 k0 | n0-7 k+16B | n8-15 k0 | n8-15 k+16B]
    const uint32_t bLane =
        (uint32_t)(wn * 32 + ((lane >> 4) & 1) * 8 + (lane & 7)) * TSTRIDE
        + (uint32_t)((lane >> 3) & 1) * 16;

    for (int t = 0; t < NT; ++t) {
        if (t + 1 < NT) {
            cp_tile(sbase + TILEB + ((t + 1) & 1) * TILEB, jbase + (t + 1) * 128);
            CP_COMMIT();
            if (tid < 128)
                s_pj[(t + 1) & 1][tid] = g_pieces[jbase + (t + 1) * 128 + tid];
        }

        // ---- MMA: 128x128 <- A(128x256) * B(128x256)^T ----
        float acc[4][4][4];
        #pragma unroll
        for (int mt = 0; mt < 4; mt++)
            #pragma unroll
            for (int nt = 0; nt < 4; nt++)
                #pragma unroll
                for (int e = 0; e < 4; e++) acc[mt][nt][e] = 0.f;

        const uint32_t bTile = sbase + TILEB + (uint32_t)(t & 1) * TILEB + bLane;

        #pragma unroll
        for (int ks = 0; ks < 16; ks++) {
            uint32_t a[4][4], b[4][2];
            #pragma unroll
            for (int mt = 0; mt < 4; mt++)
                ldsm4(aLane + (uint32_t)mt * (16 * TSTRIDE) + ks * 32, a[mt]);
            #pragma unroll
            for (int p = 0; p < 2; p++) {
                uint32_t r[4];
                ldsm4(bTile + (uint32_t)p * (16 * TSTRIDE) + ks * 32, r);
                b[p * 2][0]     = r[0];
                b[p * 2][1]     = r[1];
                b[p * 2 + 1][0] = r[2];
                b[p * 2 + 1][1] = r[3];
            }
            #pragma unroll
            for (int mt = 0; mt < 4; mt++)
                #pragma unroll
                for (int nt = 0; nt < 4; nt++)
                    mma16816(acc[mt][nt], a[mt], b[nt]);
        }

        // ---- fused epilogue ----
        const int* pjrow = s_pj[t & 1];
        const int j0 = jbase + t * 128 + wn * 32 + (lane & 3) * 2;
        int pjc[8];
        #pragma unroll
        for (int nt = 0; nt < 4; nt++) {
            pjc[nt * 2]     = pjrow[wn * 32 + nt * 8 + (lane & 3) * 2];
            pjc[nt * 2 + 1] = pjrow[wn * 32 + nt * 8 + (lane & 3) * 2 + 1];
        }
        #pragma unroll
        for (int mt = 0; mt < 4; mt++)
            #pragma unroll
            for (int h = 0; h < 2; h++) {
                const int ridx = mt * 2 + h;
                const int myp = mypc[ridx];
                float na = 0.f;
                #pragma unroll
                for (int nt = 0; nt < 4; nt++)
                    #pragma unroll
                    for (int cc = 0; cc < 2; cc++) {
                        float dot = acc[mt][nt][h * 2 + cc];
                        float e = ex2(fmaf(dot, C2EXP, -C2EXP));
                        bool same = (pjc[nt * 2 + cc] == myp);
                        na += same ? 0.f : e;
                        if (same) {
                            int jg = j0 + nt * 8 + cc;
                            if (jg != igr[ridx]) {
                                if (pcnt[ridx] < CAP)
                                    pptr[ridx][pcnt[ridx]] = dot * INV_T;
                                pcnt[ridx]++;
                            }
                        }
                    }
                negacc[ridx] += na;
            }

        CP_WAIT0();
        __syncthreads();
    }

    // ---- write per-(row, region) results ----
    #pragma unroll
    for (int ridx = 0; ridx < 8; ridx++) {
        float v = negacc[ridx];
        v += __shfl_xor_sync(0xffffffffu, v, 1);
        v += __shfl_xor_sync(0xffffffffu, v, 2);
        if ((lane & 3) == 0)
            g_negS[region * NROWS + igr[ridx]] = v;
        g_posCnt[(igr[ridx] * REGIONS + region) * 4 + (lane & 3)] =
            (pcnt[ridx] > CAP) ? CAP : pcnt[ridx];
    }
}

// ---------------- kernel 3: ranking loss partials ----------------
__global__ void ranking_kernel(const float* __restrict__ logits,
                               const float* __restrict__ la,
                               const float* __restrict__ lb) {
    __shared__ float ssum[256];
    __shared__ int   scnt[256];
    int tid = threadIdx.x;
    float sum = 0.f; int cnt = 0;
    for (int i = blockIdx.x * 256 + tid; i < BATCH * NDIMS; i += 64 * 256) {
        float diff = la[i] - lb[i];
        if (fabsf(diff) >= 0.05f) {
            float t = (diff > 0.f ? 0.9f : 0.f) + 0.05f;
            float l = logits[i];
            sum += fmaxf(l, 0.f) - l * t + log1pf(__expf(-fabsf(l)));
            cnt++;
        }
    }
    ssum[tid] = sum; scnt[tid] = cnt;
    __syncthreads();
    for (int o = 128; o; o >>= 1) {
        if (tid < o) { ssum[tid] += ssum[tid + o]; scnt[tid] += scnt[tid + o]; }
        __syncthreads();
    }
    if (tid == 0) { g_rankS[blockIdx.x] = ssum[0]; g_rankC[blockIdx.x] = scnt[0]; }
}

// ---------------- kernel 4: per-row merge (warp per row) ----------------
__global__ void final_row_kernel() {
    const int warp = threadIdx.x >> 5;
    const int lane = threadIdx.x & 31;
    const int i = blockIdx.x * 8 + warp;
    const int r  = lane >> 2;
    const int qd = lane & 3;

    float S = (qd == 0) ? g_negS[r * NROWS + i] : 0.f;
    #pragma unroll
    for (int o = 16; o; o >>= 1) S += __shfl_xor_sync(0xffffffffu, S, o);

    float sum = 0.f; int cnt = 0;
    if (S > 0.f) {
        float nl = INV_T + logf(S);
        int n = g_posCnt[(i * REGIONS + r) * 4 + qd];
        const float* pb = g_posSim + ((size_t)i * REGIONS + r) * (4 * CAP) + qd * CAP;
        cnt = n;
        for (int s = 0; s < n; s++) {
            float d = nl - pb[s];
            sum += (d > 0.f) ? (d + log1pf(__expf(-d))) : log1pf(__expf(d));
        }
    }
    #pragma unroll
    for (int o = 16; o; o >>= 1) {
        sum += __shfl_xor_sync(0xffffffffu, sum, o);
        cnt += __shfl_xor_sync(0xffffffffu, cnt, o);
    }
    if (lane == 0) { g_rowSum[i] = sum; g_rowCnt[i] = cnt; }
}

// ---------------- kernel 5: final deterministic reduce ----------------
__global__ void final_kernel(float* __restrict__ out, int out_size) {
    __shared__ float ssum[256];
    __shared__ int   scnt[256];
    int tid = threadIdx.x;
    float sum = 0.f; int cnt = 0;
    for (int i = tid; i < NROWS; i += 256) { sum += g_rowSum[i]; cnt += g_rowCnt[i]; }
    ssum[tid] = sum; scnt[tid] = cnt;
    __syncthreads();
    for (int o = 128; o; o >>= 1) {
        if (tid < o) { ssum[tid] += ssum[tid + o]; scnt[tid] += scnt[tid + o]; }
        __syncthreads();
    }
    if (tid == 0) {
        float rs = 0.f; int rc = 0;
        for (int b = 0; b < 64; b++) { rs += g_rankS[b]; rc += g_rankC[b]; }
        float lcon  = (scnt[0] > 0) ? (ssum[0] / (float)scnt[0]) : 0.f;
        float lrank = (rc > 0) ? (rs / (float)rc) : 0.f;
        out[0] = lrank + 0.3f * lcon;
        if (out_size > 1) out[1] = lrank;
        if (out_size > 2) out[2] = lcon;
    }
}

// ---------------- launch ----------------
extern "C" void kernel_launch(void* const* d_in, const int* in_sizes, int n_in,
                              void* d_out, int out_size) {
    const float* za     = (const float*)d_in[0];
    const float* zb     = (const float*)d_in[1];
    const float* logits = (const float*)d_in[2];
    const float* la     = (const float*)d_in[3];
    const float* lb     = (const float*)d_in[4];
    const int*   pa     = (const int*)d_in[5];
    const int*   pb     = (const int*)d_in[6];
    float* out = (float*)d_out;

    const int dynSmem = 3 * TILEB;   // A + B0 + B1 = 202752 bytes
    cudaFuncSetAttribute(simlse_kernel,
                         cudaFuncAttributeMaxDynamicSharedMemorySize, dynSmem);

    normalize_kernel<<<NROWS / 8, 256>>>(za, zb, pa, pb);
    ranking_kernel<<<64, 256>>>(logits, la, lb);
    simlse_kernel<<<dim3(NROWS / IBLK, JSPLIT), 256, dynSmem>>>();
    final_row_kernel<<<NROWS / 8, 256>>>();
    final_kernel<<<1, 256>>>(out, out_size);
}

// round 5
// speedup vs baseline: 10.2250x; 1.0039x over previous
#include <cuda_runtime.h>
#include <cuda_bf16.h>
#include <cstdint>

// ---------------- problem constants ----------------
#define BATCH    4096
#define NDIMS    19
#define D        256
#define NROWS    8192
#define JSPLIT   2
#define JCHUNK   (NROWS / JSPLIT)      // 4096
#define NT       (JCHUNK / 128)        // 32 j-tiles per CTA
#define IBLK     128
#define INV_T    14.285714285714286f
#define C2EXP    (14.285714285714286f * 1.4426950408889634f)   // INV_T * log2(e)
#define REGIONS  16                    // JSPLIT * 8 n-warps
#define CAP      8                     // positive slots per (row, region, quad)
#define TSTRIDE  528                   // padded row stride (bytes) -> conflict-free
#define TILEB    (128 * TSTRIDE)       // 67584 bytes per tile
#define NTHREADS 512

// ---------------- device scratch ----------------
__device__ uint32_t g_Zbf[NROWS * D / 2];       // normalized bf16 rows (2 per u32)
__device__ int      g_pieces[NROWS];
__device__ float    g_negS[REGIONS * NROWS];
__device__ int      g_posCnt[NROWS * REGIONS * 4];
__device__ float    g_posSim[(size_t)NROWS * REGIONS * 4 * CAP];   // 16 MB
__device__ float    g_rowSum[NROWS];
__device__ int      g_rowCnt[NROWS];
__device__ float    g_rankS[64];
__device__ int      g_rankC[64];

// ---------------- helpers ----------------
__device__ __forceinline__ uint32_t smem_u32(const void* p) {
    return (uint32_t)__cvta_generic_to_shared(p);
}
__device__ __forceinline__ float ex2(float x) {
    float r;
    asm("ex2.approx.f32 %0, %1;" : "=f"(r) : "f"(x));
    return r;
}
__device__ __forceinline__ void mma16816(float d[4], const uint32_t a[4],
                                         const uint32_t b[2]) {
    asm volatile(
        "mma.sync.aligned.m16n8k16.row.col.f32.bf16.bf16.f32 "
        "{%0,%1,%2,%3}, {%4,%5,%6,%7}, {%8,%9}, {%0,%1,%2,%3};\n"
        : "+f"(d[0]), "+f"(d[1]), "+f"(d[2]), "+f"(d[3])
        : "r"(a[0]), "r"(a[1]), "r"(a[2]), "r"(a[3]), "r"(b[0]), "r"(b[1]));
}
__device__ __forceinline__ void ldsm4(uint32_t addr, uint32_t r[4]) {
    asm volatile("ldmatrix.sync.aligned.m8n8.x4.shared.b16 {%0,%1,%2,%3}, [%4];"
                 : "=r"(r[0]), "=r"(r[1]), "=r"(r[2]), "=r"(r[3]) : "r"(addr));
}
__device__ __forceinline__ void cp16(uint32_t dst, const void* src) {
    uint64_t gs;
    asm("cvta.to.global.u64 %0, %1;" : "=l"(gs) : "l"(src));
    asm volatile("cp.async.cg.shared.global [%0], [%1], 16;" :: "r"(dst), "l"(gs));
}
#define CP_COMMIT() asm volatile("cp.async.commit_group;" ::: "memory")
#define CP_WAIT0()  asm volatile("cp.async.wait_group 0;" ::: "memory")

// load 128x256 bf16 tile into padded smem layout (512 threads)
__device__ __forceinline__ void cp_tile(uint32_t dstBase, int row0) {
    const char* src = (const char*)g_Zbf + (size_t)row0 * 512;
    #pragma unroll
    for (int it = 0; it < 8; it++) {
        int idx = it * NTHREADS + threadIdx.x;
        int r = idx >> 5, c = idx & 31;
        cp16(dstBase + r * TSTRIDE + c * 16, src + r * 512 + c * 16);
    }
}

// ---------------- kernel 1: normalize -> bf16 ----------------
__global__ void normalize_kernel(const float* __restrict__ za,
                                 const float* __restrict__ zb,
                                 const int*   __restrict__ pa,
                                 const int*   __restrict__ pb) {
    int warp = threadIdx.x >> 5;
    int lane = threadIdx.x & 31;
    int row  = blockIdx.x * 8 + warp;
    const float* src = (row < BATCH) ? (za + (size_t)row * D)
                                     : (zb + (size_t)(row - BATCH) * D);
    int k0 = lane * 4;
    float4 v0 = *(const float4*)(src + k0);
    float4 v1 = *(const float4*)(src + k0 + 128);
    float ss = v0.x*v0.x + v0.y*v0.y + v0.z*v0.z + v0.w*v0.w
             + v1.x*v1.x + v1.y*v1.y + v1.z*v1.z + v1.w*v1.w;
    #pragma unroll
    for (int off = 16; off; off >>= 1) ss += __shfl_xor_sync(0xffffffffu, ss, off);
    float inv = 1.0f / fmaxf(sqrtf(ss), 1e-8f);

    __nv_bfloat162 b0 = __floats2bfloat162_rn(v0.x * inv, v0.y * inv);
    __nv_bfloat162 b1 = __floats2bfloat162_rn(v0.z * inv, v0.w * inv);
    __nv_bfloat162 b2 = __floats2bfloat162_rn(v1.x * inv, v1.y * inv);
    __nv_bfloat162 b3 = __floats2bfloat162_rn(v1.z * inv, v1.w * inv);
    uint32_t* dst = g_Zbf + (size_t)row * 128;
    dst[lane * 2]          = *reinterpret_cast<uint32_t*>(&b0);
    dst[lane * 2 + 1]      = *reinterpret_cast<uint32_t*>(&b1);
    dst[64 + lane * 2]     = *reinterpret_cast<uint32_t*>(&b2);
    dst[64 + lane * 2 + 1] = *reinterpret_cast<uint32_t*>(&b3);
    if (lane == 0)
        g_pieces[row] = (row < BATCH) ? pa[row] : pb[row - BATCH];
}

// ---------------- kernel 2: HMMA GEMM + fused masked LSE (16 warps) ----------------
__global__ void __launch_bounds__(NTHREADS, 1) simlse_kernel() {
    extern __shared__ uint8_t dsm[];
    __shared__ int s_pi[128];
    __shared__ int s_pj[2][128];

    const int tid  = threadIdx.x;
    const int warp = tid >> 5;
    const int lane = tid & 31;
    const int wm = warp >> 3;         // 0..1 (m)
    const int wn = warp & 7;          // 0..7 (n)
    const int q  = lane >> 2;         // 0..7

    const int ib = blockIdx.x, js = blockIdx.y;
    const int i0 = ib * IBLK;
    const int jbase = js * JCHUNK;
    const int region = js * 8 + wn;

    const uint32_t sbase = smem_u32(dsm);

    if (tid < 128) {
        s_pi[tid]    = g_pieces[i0 + tid];
        s_pj[0][tid] = g_pieces[jbase + tid];
    }

    cp_tile(sbase, i0);               // A tile at offset 0
    cp_tile(sbase + TILEB, jbase);    // B0
    CP_COMMIT();
    CP_WAIT0();
    __syncthreads();

    // per-lane constants: 8 i-rows per lane (4 mt x 2 halves)
    int mypc[8], igr[8];
    #pragma unroll
    for (int mt = 0; mt < 4; mt++)
        #pragma unroll
        for (int h = 0; h < 2; h++) {
            int ridx = mt * 2 + h;
            int rloc = wm * 64 + mt * 16 + q + 8 * h;
            mypc[ridx] = s_pi[rloc];
            igr[ridx]  = i0 + rloc;
        }

    float negacc[8];
    int   pcnt[8];
    #pragma unroll
    for (int r = 0; r < 8; r++) { negacc[r] = 0.f; pcnt[r] = 0; }

    // ldmatrix lane addresses
    // A (.x4): groups [m0-7 k0 | m8-15 k0 | m0-7 k+16B | m8-15 k+16B]
    const uint32_t aLane = sbase
        + (uint32_t)(wm * 64 + (lane & 15)) * TSTRIDE + (uint32_t)(lane >> 4) * 16;
    // B (.x4): rows wn*16 + {0..15}: groups [n0-7 k0 | n0-7 k16 | n8-15 k0 | n8-15 k16]
    const uint32_t bLane =
        (uint32_t)(wn * 16 + ((lane >> 4) & 1) * 8 + (lane & 7)) * TSTRIDE
        + (uint32_t)((lane >> 3) & 1) * 16;

    for (int t = 0; t < NT; ++t) {
        if (t + 1 < NT) {
            cp_tile(sbase + TILEB + ((t + 1) & 1) * TILEB, jbase + (t + 1) * 128);
            CP_COMMIT();
            if (tid < 128)
                s_pj[(t + 1) & 1][tid] = g_pieces[jbase + (t + 1) * 128 + tid];
        }

        // ---- MMA: warp tile 64(m) x 16(n), K=256 ----
        float acc[4][2][4];
        #pragma unroll
        for (int mt = 0; mt < 4; mt++)
            #pragma unroll
            for (int nt = 0; nt < 2; nt++)
                #pragma unroll
                for (int e = 0; e < 4; e++) acc[mt][nt][e] = 0.f;

        const uint32_t bTile = sbase + TILEB + (uint32_t)(t & 1) * TILEB + bLane;

        #pragma unroll
        for (int ks = 0; ks < 16; ks++) {
            uint32_t a[4][4], b[2][2];
            #pragma unroll
            for (int mt = 0; mt < 4; mt++)
                ldsm4(aLane + (uint32_t)mt * (16 * TSTRIDE) + ks * 32, a[mt]);
            {
                uint32_t r[4];
                ldsm4(bTile + ks * 32, r);
                b[0][0] = r[0]; b[0][1] = r[1];
                b[1][0] = r[2]; b[1][1] = r[3];
            }
            #pragma unroll
            for (int mt = 0; mt < 4; mt++)
                #pragma unroll
                for (int nt = 0; nt < 2; nt++)
                    mma16816(acc[mt][nt], a[mt], b[nt]);
        }

        // ---- fused epilogue ----
        const int* pjrow = s_pj[t & 1];
        const int j0 = jbase + t * 128 + wn * 16 + (lane & 3) * 2;
        int pjc[4];
        #pragma unroll
        for (int nt = 0; nt < 2; nt++) {
            pjc[nt * 2]     = pjrow[wn * 16 + nt * 8 + (lane & 3) * 2];
            pjc[nt * 2 + 1] = pjrow[wn * 16 + nt * 8 + (lane & 3) * 2 + 1];
        }
        #pragma unroll
        for (int mt = 0; mt < 4; mt++)
            #pragma unroll
            for (int h = 0; h < 2; h++) {
                const int ridx = mt * 2 + h;
                const int myp = mypc[ridx];
                float na = 0.f;
                #pragma unroll
                for (int nt = 0; nt < 2; nt++)
                    #pragma unroll
                    for (int cc = 0; cc < 2; cc++) {
                        float dot = acc[mt][nt][h * 2 + cc];
                        float e = ex2(fmaf(dot, C2EXP, -C2EXP));
                        bool same = (pjc[nt * 2 + cc] == myp);
                        na += same ? 0.f : e;
                        if (same) {
                            int jg = j0 + nt * 8 + cc;
                            if (jg != igr[ridx]) {
                                if (pcnt[ridx] < CAP) {
                                    float* pp = g_posSim
                                        + ((size_t)igr[ridx] * REGIONS + region) * (4 * CAP)
                                        + (lane & 3) * CAP + pcnt[ridx];
                                    *pp = dot * INV_T;
                                }
                                pcnt[ridx]++;
                            }
                        }
                    }
                negacc[ridx] += na;
            }

        CP_WAIT0();
        __syncthreads();
    }

    // ---- write per-(row, region) results ----
    #pragma unroll
    for (int ridx = 0; ridx < 8; ridx++) {
        float v = negacc[ridx];
        v += __shfl_xor_sync(0xffffffffu, v, 1);
        v += __shfl_xor_sync(0xffffffffu, v, 2);
        if ((lane & 3) == 0)
            g_negS[region * NROWS + igr[ridx]] = v;
        g_posCnt[(igr[ridx] * REGIONS + region) * 4 + (lane & 3)] =
            (pcnt[ridx] > CAP) ? CAP : pcnt[ridx];
    }
}

// ---------------- kernel 3: ranking loss partials ----------------
__global__ void ranking_kernel(const float* __restrict__ logits,
                               const float* __restrict__ la,
                               const float* __restrict__ lb) {
    __shared__ float ssum[256];
    __shared__ int   scnt[256];
    int tid = threadIdx.x;
    float sum = 0.f; int cnt = 0;
    for (int i = blockIdx.x * 256 + tid; i < BATCH * NDIMS; i += 64 * 256) {
        float diff = la[i] - lb[i];
        if (fabsf(diff) >= 0.05f) {
            float t = (diff > 0.f ? 0.9f : 0.f) + 0.05f;
            float l = logits[i];
            sum += fmaxf(l, 0.f) - l * t + log1pf(__expf(-fabsf(l)));
            cnt++;
        }
    }
    ssum[tid] = sum; scnt[tid] = cnt;
    __syncthreads();
    for (int o = 128; o; o >>= 1) {
        if (tid < o) { ssum[tid] += ssum[tid + o]; scnt[tid] += scnt[tid + o]; }
        __syncthreads();
    }
    if (tid == 0) { g_rankS[blockIdx.x] = ssum[0]; g_rankC[blockIdx.x] = scnt[0]; }
}

// ---------------- kernel 4: per-row merge (warp per row) ----------------
__global__ void final_row_kernel() {
    const int warp = threadIdx.x >> 5;
    const int lane = threadIdx.x & 31;
    const int i = blockIdx.x * 8 + warp;
    const int r    = lane >> 1;       // region 0..15
    const int half = lane & 1;        // quad pair

    float S = (half == 0) ? g_negS[r * NROWS + i] : 0.f;
    #pragma unroll
    for (int o = 16; o; o >>= 1) S += __shfl_xor_sync(0xffffffffu, S, o);

    float sum = 0.f; int cnt = 0;
    if (S > 0.f) {
        float nl = INV_T + logf(S);
        #pragma unroll
        for (int k = 0; k < 2; k++) {
            int qd = half * 2 + k;
            int n = g_posCnt[(i * REGIONS + r) * 4 + qd];
            const float* pb = g_posSim + ((size_t)i * REGIONS + r) * (4 * CAP) + qd * CAP;
            cnt += n;
            for (int s = 0; s < n; s++) {
                float d = nl - pb[s];
                sum += (d > 0.f) ? (d + log1pf(__expf(-d))) : log1pf(__expf(d));
            }
        }
    }
    #pragma unroll
    for (int o = 16; o; o >>= 1) {
        sum += __shfl_xor_sync(0xffffffffu, sum, o);
        cnt += __shfl_xor_sync(0xffffffffu, cnt, o);
    }
    if (lane == 0) { g_rowSum[i] = sum; g_rowCnt[i] = cnt; }
}

// ---------------- kernel 5: final deterministic reduce ----------------
__global__ void final_kernel(float* __restrict__ out, int out_size) {
    __shared__ float ssum[256];
    __shared__ int   scnt[256];
    int tid = threadIdx.x;
    float sum = 0.f; int cnt = 0;
    for (int i = tid; i < NROWS; i += 256) { sum += g_rowSum[i]; cnt += g_rowCnt[i]; }
    ssum[tid] = sum; scnt[tid] = cnt;
    __syncthreads();
    for (int o = 128; o; o >>= 1) {
        if (tid < o) { ssum[tid] += ssum[tid + o]; scnt[tid] += scnt[tid + o]; }
        __syncthreads();
    }
    if (tid == 0) {
        float rs = 0.f; int rc = 0;
        for (int b = 0; b < 64; b++) { rs += g_rankS[b]; rc += g_rankC[b]; }
        float lcon  = (scnt[0] > 0) ? (ssum[0] / (float)scnt[0]) : 0.f;
        float lrank = (rc > 0) ? (rs / (float)rc) : 0.f;
        out[0] = lrank + 0.3f * lcon;
        if (out_size > 1) out[1] = lrank;
        if (out_size > 2) out[2] = lcon;
    }
}

// ---------------- launch ----------------
extern "C" void kernel_launch(void* const* d_in, const int* in_sizes, int n_in,
                              void* d_out, int out_size) {
    const float* za     = (const float*)d_in[0];
    const float* zb     = (const float*)d_in[1];
    const float* logits = (const float*)d_in[2];
    const float* la     = (const float*)d_in[3];
    const float* lb     = (const float*)d_in[4];
    const int*   pa     = (const int*)d_in[5];
    const int*   pb     = (const int*)d_in[6];
    float* out = (float*)d_out;

    const int dynSmem = 3 * TILEB;   // A + B0 + B1 = 202752 bytes
    cudaFuncSetAttribute(simlse_kernel,
                         cudaFuncAttributeMaxDynamicSharedMemorySize, dynSmem);

    normalize_kernel<<<NROWS / 8, 256>>>(za, zb, pa, pb);
    ranking_kernel<<<64, 256>>>(logits, la, lb);
    simlse_kernel<<<dim3(NROWS / IBLK, JSPLIT), NTHREADS, dynSmem>>>();
    final_row_kernel<<<NROWS / 8, 256>>>();
    final_kernel<<<1, 256>>>(out, out_size);
}

// round 6
// speedup vs baseline: 13.9545x; 1.3647x over previous
#include <cuda_runtime.h>
#include <cuda_bf16.h>
#include <cstdint>

// ---------------- problem constants ----------------
#define BATCH    4096
#define NDIMS    19
#define D        256
#define NROWS    8192
#define NBLK     64                    // 64 row-blocks of 128
#define NUNITS   2080                  // NBLK*(NBLK+1)/2 block pairs (jb>=ib)
#define NCTA     148
#define INV_T    14.285714285714286f
#define C2EXP    (14.285714285714286f * 1.4426950408889634f)   // INV_T * log2(e)
#define CAPR     32                    // positive slots per row
#define NTHREADS 512
#define TILEB    65536                 // 128 rows x 512 bytes

// ---------------- device scratch ----------------
__device__ uint32_t g_Zbf[NROWS * D / 2];     // normalized bf16 rows (2 per u32)
__device__ int      g_pieces[NROWS];
__device__ float    g_negP[(size_t)NROWS * 1024];   // per-(row, block*16+warp) partials, 32MB
__device__ float    g_posv[NROWS * CAPR];
__device__ int      g_pcnt[NROWS];
__device__ float    g_rowSum[NROWS];
__device__ int      g_rowCnt[NROWS];
__device__ float    g_rankS[64];
__device__ int      g_rankC[64];

// ---------------- helpers ----------------
__device__ __forceinline__ uint32_t smem_u32(const void* p) {
    return (uint32_t)__cvta_generic_to_shared(p);
}
__device__ __forceinline__ float ex2(float x) {
    float r;
    asm("ex2.approx.f32 %0, %1;" : "=f"(r) : "f"(x));
    return r;
}
__device__ __forceinline__ void mma16816(float d[4], const uint32_t a[4],
                                         const uint32_t b[2]) {
    asm volatile(
        "mma.sync.aligned.m16n8k16.row.col.f32.bf16.bf16.f32 "
        "{%0,%1,%2,%3}, {%4,%5,%6,%7}, {%8,%9}, {%0,%1,%2,%3};\n"
        : "+f"(d[0]), "+f"(d[1]), "+f"(d[2]), "+f"(d[3])
        : "r"(a[0]), "r"(a[1]), "r"(a[2]), "r"(a[3]), "r"(b[0]), "r"(b[1]));
}
__device__ __forceinline__ void ldsm4(uint32_t addr, uint32_t r[4]) {
    asm volatile("ldmatrix.sync.aligned.m8n8.x4.shared.b16 {%0,%1,%2,%3}, [%4];"
                 : "=r"(r[0]), "=r"(r[1]), "=r"(r[2]), "=r"(r[3]) : "r"(addr));
}
__device__ __forceinline__ void cp16(uint32_t dst, const void* src) {
    uint64_t gs;
    asm("cvta.to.global.u64 %0, %1;" : "=l"(gs) : "l"(src));
    asm volatile("cp.async.cg.shared.global [%0], [%1], 16;" :: "r"(dst), "l"(gs));
}
#define CP_COMMIT() asm volatile("cp.async.commit_group;" ::: "memory")
#define CP_WAIT0()  asm volatile("cp.async.wait_group 0;" ::: "memory")
#define CP_WAIT1()  asm volatile("cp.async.wait_group 1;" ::: "memory")

// 128x256 bf16 tile -> 512B rows with XOR-16B-chunk swizzle: chunk' = chunk ^ (row&7)
__device__ __forceinline__ void cp_tile(uint32_t dstBase, int row0) {
    const char* src = (const char*)g_Zbf + (size_t)row0 * 512;
    #pragma unroll
    for (int it = 0; it < 8; it++) {
        int idx = it * NTHREADS + threadIdx.x;
        int r = idx >> 5, ch = idx & 31;
        cp16(dstBase + r * 512 + ((ch ^ (r & 7)) << 4), src + r * 512 + ch * 16);
    }
}

// ---------------- kernel 1: normalize -> bf16 (+ zero positive counters) ----------------
__global__ void normalize_kernel(const float* __restrict__ za,
                                 const float* __restrict__ zb,
                                 const int*   __restrict__ pa,
                                 const int*   __restrict__ pb) {
    int warp = threadIdx.x >> 5;
    int lane = threadIdx.x & 31;
    int row  = blockIdx.x * 8 + warp;
    const float* src = (row < BATCH) ? (za + (size_t)row * D)
                                     : (zb + (size_t)(row - BATCH) * D);
    int k0 = lane * 4;
    float4 v0 = *(const float4*)(src + k0);
    float4 v1 = *(const float4*)(src + k0 + 128);
    float ss = v0.x*v0.x + v0.y*v0.y + v0.z*v0.z + v0.w*v0.w
             + v1.x*v1.x + v1.y*v1.y + v1.z*v1.z + v1.w*v1.w;
    #pragma unroll
    for (int off = 16; off; off >>= 1) ss += __shfl_xor_sync(0xffffffffu, ss, off);
    float inv = 1.0f / fmaxf(sqrtf(ss), 1e-8f);

    __nv_bfloat162 b0 = __floats2bfloat162_rn(v0.x * inv, v0.y * inv);
    __nv_bfloat162 b1 = __floats2bfloat162_rn(v0.z * inv, v0.w * inv);
    __nv_bfloat162 b2 = __floats2bfloat162_rn(v1.x * inv, v1.y * inv);
    __nv_bfloat162 b3 = __floats2bfloat162_rn(v1.z * inv, v1.w * inv);
    uint32_t* dst = g_Zbf + (size_t)row * 128;
    dst[lane * 2]          = *reinterpret_cast<uint32_t*>(&b0);
    dst[lane * 2 + 1]      = *reinterpret_cast<uint32_t*>(&b1);
    dst[64 + lane * 2]     = *reinterpret_cast<uint32_t*>(&b2);
    dst[64 + lane * 2 + 1] = *reinterpret_cast<uint32_t*>(&b3);
    if (lane == 0) {
        g_pieces[row] = (row < BATCH) ? pa[row] : pb[row - BATCH];
        g_pcnt[row]   = 0;
    }
}

// ---------------- kernel 2: symmetric HMMA GEMM + fused masked LSE ----------------
__global__ void __launch_bounds__(NTHREADS, 1) simlse_kernel() {
    extern __shared__ uint8_t dsm[];
    __shared__ int s_pi[128];
    __shared__ int s_pj[128];

    const int tid  = threadIdx.x;
    const int warp = tid >> 5;
    const int lane = tid & 31;
    const int wm = warp >> 3;         // 0..1 (m)
    const int wn = warp & 7;          // 0..7 (n)
    const int q  = lane >> 2;         // 0..7

    const uint32_t sbase = smem_u32(dsm);
    const uint32_t bufA  = sbase;
    const uint32_t bufB0 = sbase + TILEB;
    const uint32_t bufB1 = sbase + 2 * TILEB;

    // static balanced unit assignment: 2080 = 148*14 + 8
    const int c = blockIdx.x;
    const int ustart = c * 14 + (c < 8 ? c : 8);
    const int ucount = 14 + (c < 8 ? 1 : 0);

    int ib = 0, rem = ustart;
    while (rem >= NBLK - ib) { rem -= NBLK - ib; ib++; }
    int jb = ib + rem;

    cp_tile(bufA, ib * 128);
    cp_tile(bufB0, jb * 128);
    CP_COMMIT();
    if (tid < 128) s_pi[tid] = g_pieces[ib * 128 + tid];

    // ldmatrix lane bases
    const uint32_t aRow = bufA + (uint32_t)(wm * 64 + (lane & 15)) * 512;
    const uint32_t bRowOff = (uint32_t)(wn * 16 + ((lane >> 4) & 1) * 8 + (lane & 7)) * 512;
    const uint32_t ax = (uint32_t)(lane >> 4);        // A base chunk
    const uint32_t bx = (uint32_t)((lane >> 3) & 1);  // B base chunk
    const uint32_t xr = (uint32_t)(lane & 7);

    for (int un = 0; un < ucount; un++) {
        const int par = un & 1;
        int nib = ib, njb = jb + 1;
        if (njb == NBLK) { nib = ib + 1; njb = nib; }
        const bool hasNext = (un + 1 < ucount);

        if (hasNext) {
            cp_tile(par ? bufB0 : bufB1, njb * 128);
            CP_COMMIT();
            CP_WAIT1();
        } else {
            CP_WAIT0();
        }
        __syncthreads();

        if (tid < 128) s_pj[tid] = g_pieces[jb * 128 + tid];

        int mypc[8];
        #pragma unroll
        for (int mt = 0; mt < 4; mt++)
            #pragma unroll
            for (int h = 0; h < 2; h++)
                mypc[mt * 2 + h] = s_pi[wm * 64 + mt * 16 + q + 8 * h];

        // ---- MMA: warp tile 64(m) x 16(n), K=256 ----
        float acc[4][2][4];
        #pragma unroll
        for (int mt = 0; mt < 4; mt++)
            #pragma unroll
            for (int nt = 0; nt < 2; nt++)
                #pragma unroll
                for (int e = 0; e < 4; e++) acc[mt][nt][e] = 0.f;

        const uint32_t bRow = (par ? bufB1 : bufB0) + bRowOff;

        #pragma unroll
        for (int ks = 0; ks < 16; ks++) {
            const uint32_t aoff = (((ax + ks * 2) ^ xr) << 4);
            const uint32_t boff = (((bx + ks * 2) ^ xr) << 4);
            uint32_t a[4][4], b[2][2];
            #pragma unroll
            for (int mt = 0; mt < 4; mt++)
                ldsm4(aRow + (uint32_t)mt * 8192 + aoff, a[mt]);
            {
                uint32_t r[4];
                ldsm4(bRow + boff, r);
                b[0][0] = r[0]; b[0][1] = r[1];
                b[1][0] = r[2]; b[1][1] = r[3];
            }
            #pragma unroll
            for (int mt = 0; mt < 4; mt++)
                #pragma unroll
                for (int nt = 0; nt < 2; nt++)
                    mma16816(acc[mt][nt], a[mt], b[nt]);
        }
        __syncthreads();   // all MMA smem reads done; s_pj visible

        // ---- fused epilogue: row pass + column pass ----
        const bool isDiag = (ib == jb);
        int pjc[4];
        #pragma unroll
        for (int nt = 0; nt < 2; nt++)
            #pragma unroll
            for (int cc = 0; cc < 2; cc++)
                pjc[nt * 2 + cc] = s_pj[wn * 16 + nt * 8 + (lane & 3) * 2 + cc];

        const int jgBase = jb * 128 + wn * 16 + (lane & 3) * 2;
        float colacc[4] = {0.f, 0.f, 0.f, 0.f};

        #pragma unroll
        for (int mt = 0; mt < 4; mt++)
            #pragma unroll
            for (int h = 0; h < 2; h++) {
                const int rloc = wm * 64 + mt * 16 + q + 8 * h;
                const int ig = ib * 128 + rloc;
                const int myp = mypc[mt * 2 + h];
                float na = 0.f;
                #pragma unroll
                for (int nt = 0; nt < 2; nt++)
                    #pragma unroll
                    for (int cc = 0; cc < 2; cc++) {
                        float dot = acc[mt][nt][h * 2 + cc];
                        float e = ex2(fmaf(dot, C2EXP, -C2EXP));
                        bool same = (pjc[nt * 2 + cc] == myp);
                        na += same ? 0.f : e;
                        colacc[nt * 2 + cc] += same ? 0.f : e;
                        if (same) {
                            int jg = jgBase + nt * 8 + cc;
                            if (!isDiag || jg != ig) {
                                float sim = dot * INV_T;
                                int sl = atomicAdd(&g_pcnt[ig], 1);
                                if (sl < CAPR) g_posv[ig * CAPR + sl] = sim;
                                if (!isDiag) {
                                    int sl2 = atomicAdd(&g_pcnt[jg], 1);
                                    if (sl2 < CAPR) g_posv[jg * CAPR + sl2] = sim;
                                }
                            }
                        }
                    }
                na += __shfl_xor_sync(0xffffffffu, na, 1);
                na += __shfl_xor_sync(0xffffffffu, na, 2);
                if ((lane & 3) == 0)
                    g_negP[(size_t)ig * 1024 + jb * 16 + warp] = na;
            }

        if (!isDiag) {
            #pragma unroll
            for (int idx = 0; idx < 4; idx++) {
                colacc[idx] += __shfl_xor_sync(0xffffffffu, colacc[idx], 4);
                colacc[idx] += __shfl_xor_sync(0xffffffffu, colacc[idx], 8);
                colacc[idx] += __shfl_xor_sync(0xffffffffu, colacc[idx], 16);
            }
            if (lane < 4) {
                #pragma unroll
                for (int nt = 0; nt < 2; nt++)
                    #pragma unroll
                    for (int cc = 0; cc < 2; cc++) {
                        int jg = jb * 128 + wn * 16 + nt * 8 + lane * 2 + cc;
                        g_negP[(size_t)jg * 1024 + ib * 16 + warp] = colacc[nt * 2 + cc];
                    }
            }
        }

        // A switch for next unit (safe: post-MMA sync passed; epilogue doesn't touch bufA/s_pi)
        if (hasNext && nib != ib) {
            cp_tile(bufA, nib * 128);
            CP_COMMIT();
            if (tid < 128) s_pi[tid] = g_pieces[nib * 128 + tid];
        }
        ib = nib; jb = njb;
    }
}

// ---------------- kernel 3: ranking loss partials ----------------
__global__ void ranking_kernel(const float* __restrict__ logits,
                               const float* __restrict__ la,
                               const float* __restrict__ lb) {
    __shared__ float ssum[256];
    __shared__ int   scnt[256];
    int tid = threadIdx.x;
    float sum = 0.f; int cnt = 0;
    for (int i = blockIdx.x * 256 + tid; i < BATCH * NDIMS; i += 64 * 256) {
        float diff = la[i] - lb[i];
        if (fabsf(diff) >= 0.05f) {
            float t = (diff > 0.f ? 0.9f : 0.f) + 0.05f;
            float l = logits[i];
            sum += fmaxf(l, 0.f) - l * t + log1pf(__expf(-fabsf(l)));
            cnt++;
        }
    }
    ssum[tid] = sum; scnt[tid] = cnt;
    __syncthreads();
    for (int o = 128; o; o >>= 1) {
        if (tid < o) { ssum[tid] += ssum[tid + o]; scnt[tid] += scnt[tid + o]; }
        __syncthreads();
    }
    if (tid == 0) { g_rankS[blockIdx.x] = ssum[0]; g_rankC[blockIdx.x] = scnt[0]; }
}

// ---------------- kernel 4: per-row merge (warp per row) ----------------
__global__ void final_row_kernel() {
    const int warp = threadIdx.x >> 5;
    const int lane = threadIdx.x & 31;
    const int i = blockIdx.x * 8 + warp;

    const float* np = g_negP + (size_t)i * 1024;
    float S = 0.f;
    #pragma unroll
    for (int k = 0; k < 32; k++) S += np[lane + 32 * k];
    #pragma unroll
    for (int o = 16; o; o >>= 1) S += __shfl_xor_sync(0xffffffffu, S, o);

    int n = g_pcnt[i];
    if (n > CAPR) n = CAPR;
    float sum = 0.f;
    int cnt = 0;
    if (S > 0.f) {
        float nl = INV_T + logf(S);
        cnt = n;
        for (int s = lane; s < n; s += 32) {
            float d = nl - g_posv[i * CAPR + s];
            sum += (d > 0.f) ? (d + log1pf(__expf(-d))) : log1pf(__expf(d));
        }
    }
    #pragma unroll
    for (int o = 16; o; o >>= 1) sum += __shfl_xor_sync(0xffffffffu, sum, o);
    if (lane == 0) { g_rowSum[i] = sum; g_rowCnt[i] = cnt; }
}

// ---------------- kernel 5: final deterministic reduce ----------------
__global__ void final_kernel(float* __restrict__ out, int out_size) {
    __shared__ float ssum[256];
    __shared__ int   scnt[256];
    int tid = threadIdx.x;
    float sum = 0.f; int cnt = 0;
    for (int i = tid; i < NROWS; i += 256) { sum += g_rowSum[i]; cnt += g_rowCnt[i]; }
    ssum[tid] = sum; scnt[tid] = cnt;
    __syncthreads();
    for (int o = 128; o; o >>= 1) {
        if (tid < o) { ssum[tid] += ssum[tid + o]; scnt[tid] += scnt[tid + o]; }
        __syncthreads();
    }
    if (tid == 0) {
        float rs = 0.f; int rc = 0;
        for (int b = 0; b < 64; b++) { rs += g_rankS[b]; rc += g_rankC[b]; }
        float lcon  = (scnt[0] > 0) ? (ssum[0] / (float)scnt[0]) : 0.f;
        float lrank = (rc > 0) ? (rs / (float)rc) : 0.f;
        out[0] = lrank + 0.3f * lcon;
        if (out_size > 1) out[1] = lrank;
        if (out_size > 2) out[2] = lcon;
    }
}

// ---------------- launch ----------------
extern "C" void kernel_launch(void* const* d_in, const int* in_sizes, int n_in,
                              void* d_out, int out_size) {
    const float* za     = (const float*)d_in[0];
    const float* zb     = (const float*)d_in[1];
    const float* logits = (const float*)d_in[2];
    const float* la     = (const float*)d_in[3];
    const float* lb     = (const float*)d_in[4];
    const int*   pa     = (const int*)d_in[5];
    const int*   pb     = (const int*)d_in[6];
    float* out = (float*)d_out;

    const int dynSmem = 3 * TILEB;   // A + B0 + B1 = 196608 bytes
    cudaFuncSetAttribute(simlse_kernel,
                         cudaFuncAttributeMaxDynamicSharedMemorySize, dynSmem);

    normalize_kernel<<<NROWS / 8, 256>>>(za, zb, pa, pb);
    ranking_kernel<<<64, 256>>>(logits, la, lb);
    simlse_kernel<<<NCTA, NTHREADS, dynSmem>>>();
    final_row_kernel<<<NROWS / 8, 256>>>();
    final_kernel<<<1, 256>>>(out, out_size);
}